// round 12
// baseline (speedup 1.0000x reference)
#include <cuda_runtime.h>
#include <cuda_bf16.h>
#include <cuda_fp8.h>
#include <math.h>
#include <stdint.h>

// ---------------------------------------------------------------------------
// Problem constants
// ---------------------------------------------------------------------------
#define BB 32
#define NN 128
#define DD 512
#define KK 8
#define ROWS (BB * NN)                  // 4096
#define PLANE (KK * NN * NN)            // 131072
#define ALPHA_OFF ((size_t)BB * PLANE)  // 4194304

// Shared tile geometry: 128 rows x 128B data + 16B pad = 144B rows.
//   bf16 tiles: 64 k-elements per row; fp8 tiles: 128 k-elements per row.
// Row starts hit word-banks 0,4,...,28 -> conflict-free ldmatrix.
#define ROWB 144
#define TILE_BYTES (128 * ROWB)          // 18432
#define STAGE_BYTES (2 * TILE_BYTES)     // 36864
#define SMEM_BYTES (3 * STAGE_BYTES)     // 110592 (3 stages)

// Scale factors folded into the fp8 operands; they cancel in L2 normalization.
#define FUSED_SCALE 4.0f
#define W_SCALE 16.0f

// ---------------------------------------------------------------------------
// Scratch (static device globals; no cudaMalloc)
// ---------------------------------------------------------------------------
__device__ __nv_bfloat16 g_A0[(size_t)ROWS * 1024];     // concat(desc,nv) bf16
__device__ __nv_bfloat16 g_fwb[(size_t)DD * 1024];      // fusion_w bf16 [d][e]
__device__ uint8_t g_Wt8[(size_t)16 * DD * DD];         // (W^T x16) e4m3 [z][f][d]
__device__ uint8_t g_fused8[(size_t)ROWS * DD];         // (fused x4) e4m3
__device__ uint8_t g_qk8[(size_t)16 * ROWS * DD];       // q (z<8) then k, e4m3 (x64)
__device__ float g_ss[(size_t)16 * 8 * ROWS];           // partial sumsq [z][p][row]

// ---------------------------------------------------------------------------
// PTX helpers (plain sm_100-safe: HMMA/QMMA mma.sync, ldmatrix, cp.async)
// ---------------------------------------------------------------------------
__device__ __forceinline__ uint32_t smem_u32(const void* p) {
    uint32_t a;
    asm("{ .reg .u64 t; cvta.to.shared.u64 t, %1; cvt.u32.u64 %0, t; }"
        : "=r"(a) : "l"(p));
    return a;
}

__device__ __forceinline__ void cp16(uint32_t dst, const void* src) {
    asm volatile("cp.async.cg.shared.global [%0], [%1], 16;"
                 :: "r"(dst), "l"(src));
}
#define CP_COMMIT() asm volatile("cp.async.commit_group;" ::: "memory")
#define CP_WAIT1()  asm volatile("cp.async.wait_group 1;" ::: "memory")

__device__ __forceinline__ void ldsm4(uint32_t* r, uint32_t addr) {
    asm volatile("ldmatrix.sync.aligned.m8n8.x4.shared.b16 {%0,%1,%2,%3}, [%4];"
                 : "=r"(r[0]), "=r"(r[1]), "=r"(r[2]), "=r"(r[3]) : "r"(addr));
}

__device__ __forceinline__ void mma_bf16(float* d, const uint32_t* a,
                                         uint32_t b0, uint32_t b1) {
    asm volatile(
        "mma.sync.aligned.m16n8k16.row.col.f32.bf16.bf16.f32 "
        "{%0,%1,%2,%3}, {%4,%5,%6,%7}, {%8,%9}, {%0,%1,%2,%3};"
        : "+f"(d[0]), "+f"(d[1]), "+f"(d[2]), "+f"(d[3])
        : "r"(a[0]), "r"(a[1]), "r"(a[2]), "r"(a[3]), "r"(b0), "r"(b1));
}

// fp8 e4m3 MMA: m16n8k32, fp32 accumulate. Fragment layout in b16 units is
// identical to the bf16 m16n8k16 layout (2 packed fp8 = 1 b16 element).
__device__ __forceinline__ void mma_fp8(float* d, const uint32_t* a,
                                        uint32_t b0, uint32_t b1) {
    asm volatile(
        "mma.sync.aligned.m16n8k32.row.col.f32.e4m3.e4m3.f32 "
        "{%0,%1,%2,%3}, {%4,%5,%6,%7}, {%8,%9}, {%0,%1,%2,%3};"
        : "+f"(d[0]), "+f"(d[1]), "+f"(d[2]), "+f"(d[3])
        : "r"(a[0]), "r"(a[1]), "r"(a[2]), "r"(a[3]), "r"(b0), "r"(b1));
}

// Load one 128x64 bf16 A tile + B tile into a smem stage (128 threads).
__device__ __forceinline__ void load_tile128(uint32_t sdst,
                                             const __nv_bfloat16* gA, int ldA,
                                             const __nv_bfloat16* gB, int ldB,
                                             int tid) {
#pragma unroll
    for (int h = 0; h < 8; h++) {
        int c = tid + h * 128;          // 0..1023
        int row = c >> 3, q = c & 7;    // 8 x 16B chunks per 128B row
        cp16(sdst + row * ROWB + q * 16, gA + (size_t)row * ldA + q * 8);
        cp16(sdst + TILE_BYTES + row * ROWB + q * 16,
             gB + (size_t)row * ldB + q * 8);
    }
}

// Load one 128x128 fp8 A tile + B tile into a smem stage (256 threads).
__device__ __forceinline__ void load_tile8(uint32_t sdst,
                                           const uint8_t* gA,
                                           const uint8_t* gB, int tid) {
#pragma unroll
    for (int h = 0; h < 4; h++) {
        int c = tid + h * 256;          // 0..1023
        int row = c >> 3, q = c & 7;    // 8 x 16B chunks per 128B row
        cp16(sdst + row * ROWB + q * 16, gA + (size_t)row * DD + q * 16);
        cp16(sdst + TILE_BYTES + row * ROWB + q * 16,
             gB + (size_t)row * DD + q * 16);
    }
}

// Load one 128x128 fp8 A tile + B tile into a smem stage (128 threads).
__device__ __forceinline__ void load_tile8_128(uint32_t sdst,
                                               const uint8_t* gA,
                                               const uint8_t* gB, int tid) {
#pragma unroll
    for (int h = 0; h < 8; h++) {
        int c = tid + h * 128;          // 0..1023
        int row = c >> 3, q = c & 7;
        cp16(sdst + row * ROWB + q * 16, gA + (size_t)row * DD + q * 16);
        cp16(sdst + TILE_BYTES + row * ROWB + q * 16,
             gB + (size_t)row * DD + q * 16);
    }
}

// ---------------------------------------------------------------------------
// Merged prep kernel: blocks [0, 2304) convert inputs -> bf16;
// blocks [2304, 2304+4096) transpose W -> e4m3 (x16).
// ---------------------------------------------------------------------------
#define CONV_BLOCKS 2304
__global__ __launch_bounds__(256) void prep_kernel(
    const float* __restrict__ desc, const float* __restrict__ nv,
    const float* __restrict__ fw,
    const float* __restrict__ Wq, const float* __restrict__ Wk) {
    if (blockIdx.x < CONV_BLOCKS) {
        size_t base = ((size_t)blockIdx.x * 256 + threadIdx.x) * 8;
        if (base >= (size_t)(ROWS + DD) * 1024) return;
        int r = (int)(base >> 10);
        int c = (int)(base & 1023);
        const float* src;
        __nv_bfloat16* dst;
        if (r < ROWS) {
            src = (c < DD) ? (desc + (size_t)r * DD + c)
                           : (nv + (size_t)r * DD + (c - DD));
            dst = g_A0 + ((size_t)r << 10) + c;
        } else {
            src = fw + (size_t)(r - ROWS) * 1024 + c;
            dst = g_fwb + (size_t)(r - ROWS) * 1024 + c;
        }
        float4 v0 = *(const float4*)src;
        float4 v1 = *(const float4*)(src + 4);
        uint32_t pk[4];
        __nv_bfloat162 h;
        h = __float22bfloat162_rn(make_float2(v0.x, v0.y)); pk[0] = *(uint32_t*)&h;
        h = __float22bfloat162_rn(make_float2(v0.z, v0.w)); pk[1] = *(uint32_t*)&h;
        h = __float22bfloat162_rn(make_float2(v1.x, v1.y)); pk[2] = *(uint32_t*)&h;
        h = __float22bfloat162_rn(make_float2(v1.z, v1.w)); pk[3] = *(uint32_t*)&h;
        *(uint4*)dst = *(uint4*)pk;
    } else {
        __shared__ float t[32][33];
        int blk = blockIdx.x - CONV_BLOCKS;       // 0..4095 = (z*256 + xy)
        int z = blk >> 8;
        int xy = blk & 255;                        // (x*16 + y)
        int d0 = (xy >> 4) * 32, f0 = (xy & 15) * 32;
        const float* W = (z < KK) ? (Wq + (size_t)z * DD * DD)
                                  : (Wk + (size_t)(z - KK) * DD * DD);
        uint8_t* o = g_Wt8 + (size_t)z * DD * DD;
        int tx = threadIdx.x & 31, ty = threadIdx.x >> 5;
#pragma unroll
        for (int j = 0; j < 32; j += 8)
            t[ty + j][tx] = W[(size_t)(d0 + ty + j) * DD + f0 + tx];
        __syncthreads();
#pragma unroll
        for (int j = 0; j < 32; j += 8)
            o[(size_t)(f0 + ty + j) * DD + d0 + tx] =
                __nv_cvt_float_to_fp8(t[tx][ty + j] * W_SCALE,
                                      __NV_SATFINITE, __NV_E4M3);
    }
}

// ---------------------------------------------------------------------------
// Fusion GEMM (bf16 HMMA): 128x128 tile, 2x2 warps, K=1024, fp8 epilogue.
// ---------------------------------------------------------------------------
__device__ __forceinline__ void gemm_2x2_64(
    char* smem, const __nv_bfloat16* gA, int ldA,
    const __nv_bfloat16* gB, int ldB, int KT, float acc[4][8][4]) {
    const uint32_t sb = smem_u32(smem);
    const int tid = threadIdx.x, lane = tid & 31, wid = tid >> 5;
    const int wm = wid >> 1, wn = wid & 1;
    const int lr = lane & 15, lh = (lane >> 4) * 16;

    load_tile128(sb, gA, ldA, gB, ldB, tid);
    CP_COMMIT();
    load_tile128(sb + STAGE_BYTES, gA + 64, ldA, gB + 64, ldB, tid);
    CP_COMMIT();

#pragma unroll 1
    for (int kt = 0; kt < KT; kt++) {
        CP_WAIT1();
        __syncthreads();
        if (kt + 2 < KT)
            load_tile128(sb + ((kt + 2) % 3) * STAGE_BYTES,
                         gA + (kt + 2) * 64, ldA, gB + (kt + 2) * 64, ldB, tid);
        CP_COMMIT();
        const uint32_t stage = sb + (kt % 3) * STAGE_BYTES;
        const uint32_t sA = stage + (wm * 64 + lr) * ROWB + lh;
        const uint32_t sB = stage + TILE_BYTES + (wn * 64 + lr) * ROWB + lh;
#pragma unroll
        for (int ks = 0; ks < 4; ks++) {
            const int ko = ks * 32;
            uint32_t a[4][4], b[4][4];
#pragma unroll
            for (int i = 0; i < 4; i++) ldsm4(a[i], sA + i * (16 * ROWB) + ko);
#pragma unroll
            for (int j = 0; j < 4; j++) ldsm4(b[j], sB + j * (16 * ROWB) + ko);
#pragma unroll
            for (int i = 0; i < 4; i++)
#pragma unroll
                for (int j = 0; j < 4; j++) {
                    mma_bf16(acc[i][2 * j],     a[i], b[j][0], b[j][2]);
                    mma_bf16(acc[i][2 * j + 1], a[i], b[j][1], b[j][3]);
                }
        }
    }
}

__global__ __launch_bounds__(128, 2) void fusion_mma_kernel(
    const float* __restrict__ fb) {
    extern __shared__ char smem[];
    const int bn = blockIdx.x * 128, bm = blockIdx.y * 128;
    const int lane = threadIdx.x & 31, wid = threadIdx.x >> 5;
    const int wm = wid >> 1, wn = wid & 1;
    const int qr = lane >> 2, qc = (lane & 3) * 2;

    float acc[4][8][4];
#pragma unroll
    for (int i = 0; i < 4; i++)
#pragma unroll
        for (int j = 0; j < 8; j++)
#pragma unroll
            for (int e = 0; e < 4; e++) acc[i][j][e] = 0.f;

    gemm_2x2_64(smem, g_A0 + (size_t)bm * 1024, 1024,
                g_fwb + (size_t)bn * 1024, 1024, 16, acc);

    // Epilogue: (acc + bias) * FUSED_SCALE -> e4m3 into g_fused8.
#pragma unroll
    for (int mi = 0; mi < 4; mi++) {
        const int r0 = bm + wm * 64 + mi * 16 + qr;
#pragma unroll
        for (int ni = 0; ni < 8; ni++) {
            const int col = wn * 64 + ni * 8 + qc;
            const float b0 = __ldg(fb + bn + col), b1 = __ldg(fb + bn + col + 1);
            float2 p0 = {(acc[mi][ni][0] + b0) * FUSED_SCALE,
                         (acc[mi][ni][1] + b1) * FUSED_SCALE};
            float2 p1 = {(acc[mi][ni][2] + b0) * FUSED_SCALE,
                         (acc[mi][ni][3] + b1) * FUSED_SCALE};
            __nv_fp8x2_storage_t h0 =
                __nv_cvt_float2_to_fp8x2(p0, __NV_SATFINITE, __NV_E4M3);
            __nv_fp8x2_storage_t h1 =
                __nv_cvt_float2_to_fp8x2(p1, __NV_SATFINITE, __NV_E4M3);
            *(uint16_t*)(g_fused8 + (size_t)r0 * DD + bn + col) = h0;
            *(uint16_t*)(g_fused8 + (size_t)(r0 + 8) * DD + bn + col) = h1;
        }
    }
}

// ---------------------------------------------------------------------------
// Projection GEMM in fp8 (QMMA m16n8k32): 128x128 tile, 4x2 warps
// (warp tile 32x64), K-chunks of 128 fp8, 3-stage cp.async pipeline.
// Outputs q/k as e4m3 (x64 scale) + per-row partial sumsq (from fp32 acc).
// ---------------------------------------------------------------------------
__global__ __launch_bounds__(256, 2) void proj_mma_kernel() {
    extern __shared__ char smem[];
    const int bx = blockIdx.x, bn = bx * 128, bm = blockIdx.y * 128;
    const int z = blockIdx.z;
    const int tid = threadIdx.x, lane = tid & 31, wid = tid >> 5;
    const int wm = wid >> 1, wn = wid & 1;   // wm 0..3, wn 0..1
    const int lr = lane & 15, lh = (lane >> 4) * 16;

    const uint8_t* gA = g_fused8 + (size_t)bm * DD;
    const uint8_t* gB = g_Wt8 + (size_t)z * DD * DD + (size_t)bn * DD;

    float acc[2][8][4];
#pragma unroll
    for (int i = 0; i < 2; i++)
#pragma unroll
        for (int j = 0; j < 8; j++)
#pragma unroll
            for (int e = 0; e < 4; e++) acc[i][j][e] = 0.f;

    const uint32_t sb = smem_u32(smem);
    load_tile8(sb, gA, gB, tid);
    CP_COMMIT();
    load_tile8(sb + STAGE_BYTES, gA + 128, gB + 128, tid);
    CP_COMMIT();

#pragma unroll 1
    for (int kt = 0; kt < 4; kt++) {
        CP_WAIT1();
        __syncthreads();
        if (kt + 2 < 4)
            load_tile8(sb + ((kt + 2) % 3) * STAGE_BYTES,
                       gA + (kt + 2) * 128, gB + (kt + 2) * 128, tid);
        CP_COMMIT();  // unconditional: keeps wait_group accounting exact
        const uint32_t stage = sb + (kt % 3) * STAGE_BYTES;
        const uint32_t sA = stage + (wm * 32 + lr) * ROWB + lh;
        const uint32_t sB = stage + TILE_BYTES + (wn * 64 + lr) * ROWB + lh;
#pragma unroll
        for (int ks = 0; ks < 4; ks++) {
            const int ko = ks * 32;  // 32 bytes = 32 fp8 = one k32 step
            uint32_t a[2][4], b[4][4];
#pragma unroll
            for (int i = 0; i < 2; i++) ldsm4(a[i], sA + i * (16 * ROWB) + ko);
#pragma unroll
            for (int j = 0; j < 4; j++) ldsm4(b[j], sB + j * (16 * ROWB) + ko);
#pragma unroll
            for (int i = 0; i < 2; i++)
#pragma unroll
                for (int j = 0; j < 4; j++) {
                    mma_fp8(acc[i][2 * j],     a[i], b[j][0], b[j][2]);
                    mma_fp8(acc[i][2 * j + 1], a[i], b[j][1], b[j][3]);
                }
        }
    }

    uint8_t* outp = g_qk8 + (size_t)z * ROWS * DD + (size_t)bm * DD + bn;
    float* ssp = g_ss + ((size_t)(z * 8 + bx * 2 + wn) << 12) + bm;
    const int qr = lane >> 2, qc = (lane & 3) * 2;

#pragma unroll
    for (int mi = 0; mi < 2; mi++) {
        const int r0 = wm * 32 + mi * 16 + qr;
        float s0 = 0.f, s1 = 0.f;
#pragma unroll
        for (int ni = 0; ni < 8; ni++) {
            const int col = wn * 64 + ni * 8 + qc;
            const float v0 = acc[mi][ni][0], v1 = acc[mi][ni][1];
            const float v2 = acc[mi][ni][2], v3 = acc[mi][ni][3];
            s0 += v0 * v0 + v1 * v1;
            s1 += v2 * v2 + v3 * v3;
            __nv_fp8x2_storage_t h0 = __nv_cvt_float2_to_fp8x2(
                make_float2(v0, v1), __NV_SATFINITE, __NV_E4M3);
            __nv_fp8x2_storage_t h1 = __nv_cvt_float2_to_fp8x2(
                make_float2(v2, v3), __NV_SATFINITE, __NV_E4M3);
            *(uint16_t*)(outp + (size_t)r0 * DD + col) = h0;
            *(uint16_t*)(outp + (size_t)(r0 + 8) * DD + col) = h1;
        }
        s0 += __shfl_xor_sync(0xffffffffu, s0, 1);
        s0 += __shfl_xor_sync(0xffffffffu, s0, 2);
        s1 += __shfl_xor_sync(0xffffffffu, s1, 1);
        s1 += __shfl_xor_sync(0xffffffffu, s1, 2);
        if ((lane & 3) == 0) {
            ssp[r0] = s0;
            ssp[r0 + 8] = s1;
        }
    }
}

// ---------------------------------------------------------------------------
// Attention: 128x128x512 fp8 QMMA + fused norm-scaling/softmax.
// 4 warps, warp tile 32x128 so each output row stays inside one warp quad.
// (q,k carry a consistent x64 scale that cancels in normalization.)
// ---------------------------------------------------------------------------
__global__ __launch_bounds__(128, 2) void attn_mma_kernel(float* __restrict__ out) {
    extern __shared__ char smem[];
    __shared__ float sq[128], sk[128];
    const int kb = blockIdx.x, b = blockIdx.y;
    const int tid = threadIdx.x, lane = tid & 31, wid = tid >> 5;

    const uint8_t* qp = g_qk8 + ((size_t)kb * ROWS + (size_t)b * NN) * DD;
    const uint8_t* kp = g_qk8 + ((size_t)(KK + kb) * ROWS + (size_t)b * NN) * DD;

    const uint32_t sb = smem_u32(smem);
    load_tile8_128(sb, qp, kp, tid);
    CP_COMMIT();
    load_tile8_128(sb + STAGE_BYTES, qp + 128, kp + 128, tid);
    CP_COMMIT();

    // Row norms from partial sums (8 partials per row), overlapped with loads.
    {
        const float SCALE = 0.04419417382415922f;  // 1/sqrt(512)
        float s0 = 0.f, s1 = 0.f;
#pragma unroll
        for (int p = 0; p < 8; p++) {
            s0 += g_ss[((size_t)(kb * 8 + p) << 12) + b * NN + tid];
            s1 += g_ss[((size_t)((KK + kb) * 8 + p) << 12) + b * NN + tid];
        }
        sq[tid] = SCALE / fmaxf(sqrtf(s0), 1e-12f);
        sk[tid] = 1.0f / fmaxf(sqrtf(s1), 1e-12f);
    }

    float acc[2][16][4];
#pragma unroll
    for (int i = 0; i < 2; i++)
#pragma unroll
        for (int j = 0; j < 16; j++)
#pragma unroll
            for (int e = 0; e < 4; e++) acc[i][j][e] = 0.f;

    const int lr = lane & 15, lh = (lane >> 4) * 16;

#pragma unroll 1
    for (int kt = 0; kt < 4; kt++) {
        CP_WAIT1();
        __syncthreads();
        if (kt + 2 < 4)
            load_tile8_128(sb + ((kt + 2) % 3) * STAGE_BYTES,
                           qp + (kt + 2) * 128, kp + (kt + 2) * 128, tid);
        CP_COMMIT();
        const uint32_t stage = sb + (kt % 3) * STAGE_BYTES;
        const uint32_t sA = stage + (wid * 32 + lr) * ROWB + lh;
        const uint32_t sB = stage + TILE_BYTES + lr * ROWB + lh;
#pragma unroll
        for (int ks = 0; ks < 4; ks++) {
            const int ko = ks * 32;
            uint32_t a[2][4], bf[8][4];
#pragma unroll
            for (int i = 0; i < 2; i++) ldsm4(a[i], sA + i * (16 * ROWB) + ko);
#pragma unroll
            for (int j = 0; j < 8; j++) ldsm4(bf[j], sB + j * (16 * ROWB) + ko);
#pragma unroll
            for (int i = 0; i < 2; i++)
#pragma unroll
                for (int j = 0; j < 8; j++) {
                    mma_fp8(acc[i][2 * j],     a[i], bf[j][0], bf[j][2]);
                    mma_fp8(acc[i][2 * j + 1], a[i], bf[j][1], bf[j][3]);
                }
        }
    }

    // Softmax: thread owns rows wid*32 + i*16 + qr (+8), all 128 cols in quad.
    const int qr = lane >> 2, qc = (lane & 3) * 2;
#pragma unroll
    for (int i = 0; i < 2; i++) {
        const int r0 = wid * 32 + i * 16 + qr, r1 = r0 + 8;
        const float si0 = sq[r0], si1 = sq[r1];

        float m0 = -1e30f, m1 = -1e30f;
#pragma unroll
        for (int n8 = 0; n8 < 16; n8++) {
            const int col = n8 * 8 + qc;
            const float k0 = sk[col], k1 = sk[col + 1];
            acc[i][n8][0] *= si0 * k0; acc[i][n8][1] *= si0 * k1;
            acc[i][n8][2] *= si1 * k0; acc[i][n8][3] *= si1 * k1;
            m0 = fmaxf(m0, fmaxf(acc[i][n8][0], acc[i][n8][1]));
            m1 = fmaxf(m1, fmaxf(acc[i][n8][2], acc[i][n8][3]));
        }
#pragma unroll
        for (int msk = 1; msk <= 2; msk <<= 1) {
            m0 = fmaxf(m0, __shfl_xor_sync(0xffffffffu, m0, msk));
            m1 = fmaxf(m1, __shfl_xor_sync(0xffffffffu, m1, msk));
        }
        float s0 = 0.f, s1 = 0.f;
#pragma unroll
        for (int n8 = 0; n8 < 16; n8++) {
            acc[i][n8][0] = __expf(acc[i][n8][0] - m0); s0 += acc[i][n8][0];
            acc[i][n8][1] = __expf(acc[i][n8][1] - m0); s0 += acc[i][n8][1];
            acc[i][n8][2] = __expf(acc[i][n8][2] - m1); s1 += acc[i][n8][2];
            acc[i][n8][3] = __expf(acc[i][n8][3] - m1); s1 += acc[i][n8][3];
        }
#pragma unroll
        for (int msk = 1; msk <= 2; msk <<= 1) {
            s0 += __shfl_xor_sync(0xffffffffu, s0, msk);
            s1 += __shfl_xor_sync(0xffffffffu, s1, msk);
        }
        const float i0 = 1.0f / s0, i1 = 1.0f / s1;

        float* o0 = out + ALPHA_OFF + (((size_t)b * KK + kb) * NN + r0) * NN;
        float* o1 = out + ALPHA_OFF + (((size_t)b * KK + kb) * NN + r1) * NN;
#pragma unroll
        for (int n8 = 0; n8 < 16; n8++) {
            const int col = n8 * 8 + qc;
            float2 v0 = {acc[i][n8][0] * i0, acc[i][n8][1] * i0};
            float2 v1 = {acc[i][n8][2] * i1, acc[i][n8][3] * i1};
            *(float2*)(o0 + col) = v0;
            *(float2*)(o1 + col) = v1;
        }
    }
}

// ---------------------------------------------------------------------------
// bias_log = log(max(0.01 * mean_b(alpha), 1e-6)) broadcast over b (float4).
// ---------------------------------------------------------------------------
__global__ __launch_bounds__(256) void bias_kernel(float* __restrict__ out) {
    const int v = blockIdx.x * blockDim.x + threadIdx.x;  // float4 index
    if (v >= PLANE / 4) return;
    const size_t idx = (size_t)v * 4;
    float4 s = {0.f, 0.f, 0.f, 0.f};
#pragma unroll 8
    for (int b = 0; b < BB; b++) {
        float4 a = *(const float4*)(out + ALPHA_OFF + (size_t)b * PLANE + idx);
        s.x += a.x; s.y += a.y; s.z += a.z; s.w += a.w;
    }
    const float c = 0.01f / 32.0f;
    float4 bias = {logf(fmaxf(s.x * c, 1e-6f)), logf(fmaxf(s.y * c, 1e-6f)),
                   logf(fmaxf(s.z * c, 1e-6f)), logf(fmaxf(s.w * c, 1e-6f))};
#pragma unroll 8
    for (int b = 0; b < BB; b++)
        *(float4*)(out + (size_t)b * PLANE + idx) = bias;
}

// ---------------------------------------------------------------------------
// Launch
// ---------------------------------------------------------------------------
extern "C" void kernel_launch(void* const* d_in, const int* in_sizes, int n_in,
                              void* d_out, int out_size) {
    const float* desc = (const float*)d_in[0];   // [32,128,512]
    const float* nv   = (const float*)d_in[1];   // [32,128,512]
    const float* Wq   = (const float*)d_in[2];   // [8,512,512]
    const float* Wk   = (const float*)d_in[3];   // [8,512,512]
    const float* fw   = (const float*)d_in[4];   // [512,1024]
    const float* fb   = (const float*)d_in[5];   // [512]
    float* out = (float*)d_out;                  // [bias_log | alpha]

    cudaFuncSetAttribute(fusion_mma_kernel,
                         cudaFuncAttributeMaxDynamicSharedMemorySize, SMEM_BYTES);
    cudaFuncSetAttribute(proj_mma_kernel,
                         cudaFuncAttributeMaxDynamicSharedMemorySize, SMEM_BYTES);
    cudaFuncSetAttribute(attn_mma_kernel,
                         cudaFuncAttributeMaxDynamicSharedMemorySize, SMEM_BYTES);

    // Merged prep: bf16 conversions + W^T -> e4m3 (x16)
    prep_kernel<<<CONV_BLOCKS + 4096, 256>>>(desc, nv, fw, Wq, Wk);

    // fusion = [desc|nv] @ fw^T + fb  (bf16 HMMA) -> e4m3 (x4)
    fusion_mma_kernel<<<dim3(4, 32), 128, SMEM_BYTES>>>(fb);

    // q/k projections in fp8 QMMA + fused partial row-sumsq; q/k stored e4m3
    proj_mma_kernel<<<dim3(4, 32, 16), 256, SMEM_BYTES>>>();

    // logits + softmax -> alpha (fp8 QMMA + fused norm/softmax epilogue)
    attn_mma_kernel<<<dim3(8, 32), 128, SMEM_BYTES>>>(out);

    // EMA mean + log -> bias_log broadcast (float4)
    bias_kernel<<<PLANE / 4 / 256, 256>>>(out);
}

// round 13
// speedup vs baseline: 1.0321x; 1.0321x over previous
#include <cuda_runtime.h>
#include <cuda_bf16.h>
#include <cuda_fp8.h>
#include <math.h>
#include <stdint.h>

// ---------------------------------------------------------------------------
// Problem constants
// ---------------------------------------------------------------------------
#define BB 32
#define NN 128
#define DD 512
#define KK 8
#define ROWS (BB * NN)                  // 4096
#define PLANE (KK * NN * NN)            // 131072
#define ALPHA_OFF ((size_t)BB * PLANE)  // 4194304

// Shared tile geometry: 128 rows x 128B data + 16B pad = 144B rows.
//   bf16 tiles: 64 k-elements per row; fp8 tiles: 128 k-elements per row.
// Row starts hit word-banks 0,4,...,28 -> conflict-free ldmatrix.
#define ROWB 144
#define TILE_BYTES (128 * ROWB)          // 18432
#define STAGE_BYTES (2 * TILE_BYTES)     // 36864
#define SMEM_BYTES (3 * STAGE_BYTES)     // 110592 (3 stages)

// Scale factors folded into the fp8 operands; they cancel in L2 normalization.
#define FUSED_SCALE 4.0f
#define W_SCALE 16.0f

// ---------------------------------------------------------------------------
// Scratch (static device globals; no cudaMalloc)
// ---------------------------------------------------------------------------
__device__ __nv_bfloat16 g_A0[(size_t)ROWS * 1024];     // concat(desc,nv) bf16
__device__ __nv_bfloat16 g_fwb[(size_t)DD * 1024];      // fusion_w bf16 [d][e]
__device__ uint8_t g_Wt8[(size_t)16 * DD * DD];         // (W^T x16) e4m3 [z][f][d]
__device__ uint8_t g_fused8[(size_t)ROWS * DD];         // (fused x4) e4m3
__device__ __nv_bfloat16 g_qk[(size_t)16 * ROWS * DD];  // q (z<8) then k (x64 scale)
__device__ float g_ss[(size_t)16 * 8 * ROWS];           // partial sumsq [z][p][row]

// ---------------------------------------------------------------------------
// PTX helpers (plain sm_100-safe: HMMA/QMMA mma.sync, ldmatrix, cp.async)
// ---------------------------------------------------------------------------
__device__ __forceinline__ uint32_t smem_u32(const void* p) {
    uint32_t a;
    asm("{ .reg .u64 t; cvta.to.shared.u64 t, %1; cvt.u32.u64 %0, t; }"
        : "=r"(a) : "l"(p));
    return a;
}

__device__ __forceinline__ void cp16(uint32_t dst, const void* src) {
    asm volatile("cp.async.cg.shared.global [%0], [%1], 16;"
                 :: "r"(dst), "l"(src));
}
#define CP_COMMIT() asm volatile("cp.async.commit_group;" ::: "memory")
#define CP_WAIT1()  asm volatile("cp.async.wait_group 1;" ::: "memory")

__device__ __forceinline__ void ldsm4(uint32_t* r, uint32_t addr) {
    asm volatile("ldmatrix.sync.aligned.m8n8.x4.shared.b16 {%0,%1,%2,%3}, [%4];"
                 : "=r"(r[0]), "=r"(r[1]), "=r"(r[2]), "=r"(r[3]) : "r"(addr));
}

__device__ __forceinline__ void mma_bf16(float* d, const uint32_t* a,
                                         uint32_t b0, uint32_t b1) {
    asm volatile(
        "mma.sync.aligned.m16n8k16.row.col.f32.bf16.bf16.f32 "
        "{%0,%1,%2,%3}, {%4,%5,%6,%7}, {%8,%9}, {%0,%1,%2,%3};"
        : "+f"(d[0]), "+f"(d[1]), "+f"(d[2]), "+f"(d[3])
        : "r"(a[0]), "r"(a[1]), "r"(a[2]), "r"(a[3]), "r"(b0), "r"(b1));
}

// fp8 e4m3 MMA: m16n8k32, fp32 accumulate. Fragment layout in b16 units is
// identical to the bf16 m16n8k16 layout (2 packed fp8 = 1 b16 element).
__device__ __forceinline__ void mma_fp8(float* d, const uint32_t* a,
                                        uint32_t b0, uint32_t b1) {
    asm volatile(
        "mma.sync.aligned.m16n8k32.row.col.f32.e4m3.e4m3.f32 "
        "{%0,%1,%2,%3}, {%4,%5,%6,%7}, {%8,%9}, {%0,%1,%2,%3};"
        : "+f"(d[0]), "+f"(d[1]), "+f"(d[2]), "+f"(d[3])
        : "r"(a[0]), "r"(a[1]), "r"(a[2]), "r"(a[3]), "r"(b0), "r"(b1));
}

// Load one 128x64 bf16 A tile + B tile into a smem stage (128 threads).
__device__ __forceinline__ void load_tile128(uint32_t sdst,
                                             const __nv_bfloat16* gA, int ldA,
                                             const __nv_bfloat16* gB, int ldB,
                                             int tid) {
#pragma unroll
    for (int h = 0; h < 8; h++) {
        int c = tid + h * 128;          // 0..1023
        int row = c >> 3, q = c & 7;    // 8 x 16B chunks per 128B row
        cp16(sdst + row * ROWB + q * 16, gA + (size_t)row * ldA + q * 8);
        cp16(sdst + TILE_BYTES + row * ROWB + q * 16,
             gB + (size_t)row * ldB + q * 8);
    }
}

// Load one 128x128 fp8 A tile + B tile into a smem stage (256 threads).
__device__ __forceinline__ void load_tile8(uint32_t sdst,
                                           const uint8_t* gA,
                                           const uint8_t* gB, int tid) {
#pragma unroll
    for (int h = 0; h < 4; h++) {
        int c = tid + h * 256;          // 0..1023
        int row = c >> 3, q = c & 7;    // 8 x 16B chunks per 128B row
        cp16(sdst + row * ROWB + q * 16, gA + (size_t)row * DD + q * 16);
        cp16(sdst + TILE_BYTES + row * ROWB + q * 16,
             gB + (size_t)row * DD + q * 16);
    }
}

// ---------------------------------------------------------------------------
// Merged prep kernel: blocks [0, 2304) convert inputs -> bf16;
// blocks [2304, 2304+4096) transpose W -> e4m3 (x16).
// ---------------------------------------------------------------------------
#define CONV_BLOCKS 2304
__global__ __launch_bounds__(256) void prep_kernel(
    const float* __restrict__ desc, const float* __restrict__ nv,
    const float* __restrict__ fw,
    const float* __restrict__ Wq, const float* __restrict__ Wk) {
    if (blockIdx.x < CONV_BLOCKS) {
        size_t base = ((size_t)blockIdx.x * 256 + threadIdx.x) * 8;
        if (base >= (size_t)(ROWS + DD) * 1024) return;
        int r = (int)(base >> 10);
        int c = (int)(base & 1023);
        const float* src;
        __nv_bfloat16* dst;
        if (r < ROWS) {
            src = (c < DD) ? (desc + (size_t)r * DD + c)
                           : (nv + (size_t)r * DD + (c - DD));
            dst = g_A0 + ((size_t)r << 10) + c;
        } else {
            src = fw + (size_t)(r - ROWS) * 1024 + c;
            dst = g_fwb + (size_t)(r - ROWS) * 1024 + c;
        }
        float4 v0 = *(const float4*)src;
        float4 v1 = *(const float4*)(src + 4);
        uint32_t pk[4];
        __nv_bfloat162 h;
        h = __float22bfloat162_rn(make_float2(v0.x, v0.y)); pk[0] = *(uint32_t*)&h;
        h = __float22bfloat162_rn(make_float2(v0.z, v0.w)); pk[1] = *(uint32_t*)&h;
        h = __float22bfloat162_rn(make_float2(v1.x, v1.y)); pk[2] = *(uint32_t*)&h;
        h = __float22bfloat162_rn(make_float2(v1.z, v1.w)); pk[3] = *(uint32_t*)&h;
        *(uint4*)dst = *(uint4*)pk;
    } else {
        __shared__ float t[32][33];
        int blk = blockIdx.x - CONV_BLOCKS;       // 0..4095 = (z*256 + xy)
        int z = blk >> 8;
        int xy = blk & 255;                        // (x*16 + y)
        int d0 = (xy >> 4) * 32, f0 = (xy & 15) * 32;
        const float* W = (z < KK) ? (Wq + (size_t)z * DD * DD)
                                  : (Wk + (size_t)(z - KK) * DD * DD);
        uint8_t* o = g_Wt8 + (size_t)z * DD * DD;
        int tx = threadIdx.x & 31, ty = threadIdx.x >> 5;
#pragma unroll
        for (int j = 0; j < 32; j += 8)
            t[ty + j][tx] = W[(size_t)(d0 + ty + j) * DD + f0 + tx];
        __syncthreads();
#pragma unroll
        for (int j = 0; j < 32; j += 8)
            o[(size_t)(f0 + ty + j) * DD + d0 + tx] =
                __nv_cvt_float_to_fp8(t[tx][ty + j] * W_SCALE,
                                      __NV_SATFINITE, __NV_E4M3);
    }
}

// ---------------------------------------------------------------------------
// Fusion GEMM (bf16 HMMA): 128x128 tile, 2x2 warps, K=1024, fp8 epilogue.
// ---------------------------------------------------------------------------
__device__ __forceinline__ void gemm_2x2_64(
    char* smem, const __nv_bfloat16* gA, int ldA,
    const __nv_bfloat16* gB, int ldB, int KT, float acc[4][8][4]) {
    const uint32_t sb = smem_u32(smem);
    const int tid = threadIdx.x, lane = tid & 31, wid = tid >> 5;
    const int wm = wid >> 1, wn = wid & 1;
    const int lr = lane & 15, lh = (lane >> 4) * 16;

    load_tile128(sb, gA, ldA, gB, ldB, tid);
    CP_COMMIT();
    load_tile128(sb + STAGE_BYTES, gA + 64, ldA, gB + 64, ldB, tid);
    CP_COMMIT();

#pragma unroll 1
    for (int kt = 0; kt < KT; kt++) {
        CP_WAIT1();
        __syncthreads();
        if (kt + 2 < KT)
            load_tile128(sb + ((kt + 2) % 3) * STAGE_BYTES,
                         gA + (kt + 2) * 64, ldA, gB + (kt + 2) * 64, ldB, tid);
        CP_COMMIT();
        const uint32_t stage = sb + (kt % 3) * STAGE_BYTES;
        const uint32_t sA = stage + (wm * 64 + lr) * ROWB + lh;
        const uint32_t sB = stage + TILE_BYTES + (wn * 64 + lr) * ROWB + lh;
#pragma unroll
        for (int ks = 0; ks < 4; ks++) {
            const int ko = ks * 32;
            uint32_t a[4][4], b[4][4];
#pragma unroll
            for (int i = 0; i < 4; i++) ldsm4(a[i], sA + i * (16 * ROWB) + ko);
#pragma unroll
            for (int j = 0; j < 4; j++) ldsm4(b[j], sB + j * (16 * ROWB) + ko);
#pragma unroll
            for (int i = 0; i < 4; i++)
#pragma unroll
                for (int j = 0; j < 4; j++) {
                    mma_bf16(acc[i][2 * j],     a[i], b[j][0], b[j][2]);
                    mma_bf16(acc[i][2 * j + 1], a[i], b[j][1], b[j][3]);
                }
        }
    }
}

__global__ __launch_bounds__(128, 2) void fusion_mma_kernel(
    const float* __restrict__ fb) {
    extern __shared__ char smem[];
    const int bn = blockIdx.x * 128, bm = blockIdx.y * 128;
    const int lane = threadIdx.x & 31, wid = threadIdx.x >> 5;
    const int wm = wid >> 1, wn = wid & 1;
    const int qr = lane >> 2, qc = (lane & 3) * 2;

    float acc[4][8][4];
#pragma unroll
    for (int i = 0; i < 4; i++)
#pragma unroll
        for (int j = 0; j < 8; j++)
#pragma unroll
            for (int e = 0; e < 4; e++) acc[i][j][e] = 0.f;

    gemm_2x2_64(smem, g_A0 + (size_t)bm * 1024, 1024,
                g_fwb + (size_t)bn * 1024, 1024, 16, acc);

    // Epilogue: (acc + bias) * FUSED_SCALE -> e4m3 into g_fused8.
#pragma unroll
    for (int mi = 0; mi < 4; mi++) {
        const int r0 = bm + wm * 64 + mi * 16 + qr;
#pragma unroll
        for (int ni = 0; ni < 8; ni++) {
            const int col = wn * 64 + ni * 8 + qc;
            const float b0 = __ldg(fb + bn + col), b1 = __ldg(fb + bn + col + 1);
            float2 p0 = {(acc[mi][ni][0] + b0) * FUSED_SCALE,
                         (acc[mi][ni][1] + b1) * FUSED_SCALE};
            float2 p1 = {(acc[mi][ni][2] + b0) * FUSED_SCALE,
                         (acc[mi][ni][3] + b1) * FUSED_SCALE};
            __nv_fp8x2_storage_t h0 =
                __nv_cvt_float2_to_fp8x2(p0, __NV_SATFINITE, __NV_E4M3);
            __nv_fp8x2_storage_t h1 =
                __nv_cvt_float2_to_fp8x2(p1, __NV_SATFINITE, __NV_E4M3);
            *(uint16_t*)(g_fused8 + (size_t)r0 * DD + bn + col) = h0;
            *(uint16_t*)(g_fused8 + (size_t)(r0 + 8) * DD + bn + col) = h1;
        }
    }
}

// ---------------------------------------------------------------------------
// Projection GEMM in fp8 (QMMA m16n8k32): 128x128 tile, 4x2 warps
// (warp tile 32x64), K-chunks of 128 fp8, 3-stage cp.async pipeline.
// kt loop FULLY UNROLLED (KT=4) so all stage offsets/pointers are immediates.
// Outputs q/k (x64 scaled, bf16) + per-row partial sumsq.
// ---------------------------------------------------------------------------
__global__ __launch_bounds__(256, 2) void proj_mma_kernel() {
    extern __shared__ char smem[];
    const int bx = blockIdx.x, bn = bx * 128, bm = blockIdx.y * 128;
    const int z = blockIdx.z;
    const int tid = threadIdx.x, lane = tid & 31, wid = tid >> 5;
    const int wm = wid >> 1, wn = wid & 1;   // wm 0..3, wn 0..1
    const int lr = lane & 15, lh = (lane >> 4) * 16;

    const uint8_t* gA = g_fused8 + (size_t)bm * DD;
    const uint8_t* gB = g_Wt8 + (size_t)z * DD * DD + (size_t)bn * DD;

    float acc[2][8][4];
#pragma unroll
    for (int i = 0; i < 2; i++)
#pragma unroll
        for (int j = 0; j < 8; j++)
#pragma unroll
            for (int e = 0; e < 4; e++) acc[i][j][e] = 0.f;

    const uint32_t sb = smem_u32(smem);
    const uint32_t aoff = (wm * 32 + lr) * ROWB + lh;
    const uint32_t boff = TILE_BYTES + (wn * 64 + lr) * ROWB + lh;

    load_tile8(sb, gA, gB, tid);
    CP_COMMIT();
    load_tile8(sb + STAGE_BYTES, gA + 128, gB + 128, tid);
    CP_COMMIT();

#pragma unroll
    for (int kt = 0; kt < 4; kt++) {
        CP_WAIT1();
        __syncthreads();
        if (kt + 2 < 4)
            load_tile8(sb + ((kt + 2) % 3) * STAGE_BYTES,
                       gA + (kt + 2) * 128, gB + (kt + 2) * 128, tid);
        CP_COMMIT();  // unconditional: keeps wait_group accounting exact
        const uint32_t stage = sb + (kt % 3) * STAGE_BYTES;
        const uint32_t sA = stage + aoff;
        const uint32_t sB = stage + boff;
#pragma unroll
        for (int ks = 0; ks < 4; ks++) {
            const int ko = ks * 32;  // 32 bytes = 32 fp8 = one k32 step
            uint32_t a[2][4], b[4][4];
#pragma unroll
            for (int i = 0; i < 2; i++) ldsm4(a[i], sA + i * (16 * ROWB) + ko);
#pragma unroll
            for (int j = 0; j < 4; j++) ldsm4(b[j], sB + j * (16 * ROWB) + ko);
#pragma unroll
            for (int i = 0; i < 2; i++)
#pragma unroll
                for (int j = 0; j < 4; j++) {
                    mma_fp8(acc[i][2 * j],     a[i], b[j][0], b[j][2]);
                    mma_fp8(acc[i][2 * j + 1], a[i], b[j][1], b[j][3]);
                }
        }
    }

    __nv_bfloat16* outp = g_qk + (size_t)z * ROWS * DD + (size_t)bm * DD + bn;
    float* ssp = g_ss + ((size_t)(z * 8 + bx * 2 + wn) << 12) + bm;
    const int qr = lane >> 2, qc = (lane & 3) * 2;

#pragma unroll
    for (int mi = 0; mi < 2; mi++) {
        const int r0 = wm * 32 + mi * 16 + qr;
        float s0 = 0.f, s1 = 0.f;
#pragma unroll
        for (int ni = 0; ni < 8; ni++) {
            const int col = wn * 64 + ni * 8 + qc;
            const float v0 = acc[mi][ni][0], v1 = acc[mi][ni][1];
            const float v2 = acc[mi][ni][2], v3 = acc[mi][ni][3];
            s0 += v0 * v0 + v1 * v1;
            s1 += v2 * v2 + v3 * v3;
            __nv_bfloat162 h0 = __float22bfloat162_rn(make_float2(v0, v1));
            __nv_bfloat162 h1 = __float22bfloat162_rn(make_float2(v2, v3));
            *(uint32_t*)(outp + (size_t)r0 * DD + col) = *(uint32_t*)&h0;
            *(uint32_t*)(outp + (size_t)(r0 + 8) * DD + col) = *(uint32_t*)&h1;
        }
        s0 += __shfl_xor_sync(0xffffffffu, s0, 1);
        s0 += __shfl_xor_sync(0xffffffffu, s0, 2);
        s1 += __shfl_xor_sync(0xffffffffu, s1, 1);
        s1 += __shfl_xor_sync(0xffffffffu, s1, 2);
        if ((lane & 3) == 0) {
            ssp[r0] = s0;
            ssp[r0 + 8] = s1;
        }
    }
}

// ---------------------------------------------------------------------------
// Attention: 128x128x512 bf16 HMMA + fused norm-scaling/softmax.
// 4 warps, warp tile 32x128 so each output row stays inside one warp quad.
// (q,k carry a consistent x64 scale that cancels in normalization.)
// ---------------------------------------------------------------------------
__global__ __launch_bounds__(128, 2) void attn_mma_kernel(float* __restrict__ out) {
    extern __shared__ char smem[];
    __shared__ float sq[128], sk[128];
    const int kb = blockIdx.x, b = blockIdx.y;
    const int tid = threadIdx.x, lane = tid & 31, wid = tid >> 5;

    const __nv_bfloat16* qp = g_qk + ((size_t)kb * ROWS + (size_t)b * NN) * DD;
    const __nv_bfloat16* kp = g_qk + ((size_t)(KK + kb) * ROWS + (size_t)b * NN) * DD;

    const uint32_t sb = smem_u32(smem);
    load_tile128(sb, qp, DD, kp, DD, tid);
    CP_COMMIT();
    load_tile128(sb + STAGE_BYTES, qp + 64, DD, kp + 64, DD, tid);
    CP_COMMIT();

    // Row norms from partial sums (8 partials per row), overlapped with loads.
    {
        const float SCALE = 0.04419417382415922f;  // 1/sqrt(512)
        float s0 = 0.f, s1 = 0.f;
#pragma unroll
        for (int p = 0; p < 8; p++) {
            s0 += g_ss[((size_t)(kb * 8 + p) << 12) + b * NN + tid];
            s1 += g_ss[((size_t)((KK + kb) * 8 + p) << 12) + b * NN + tid];
        }
        sq[tid] = SCALE / fmaxf(sqrtf(s0), 1e-12f);
        sk[tid] = 1.0f / fmaxf(sqrtf(s1), 1e-12f);
    }

    float acc[2][16][4];
#pragma unroll
    for (int i = 0; i < 2; i++)
#pragma unroll
        for (int j = 0; j < 16; j++)
#pragma unroll
            for (int e = 0; e < 4; e++) acc[i][j][e] = 0.f;

#pragma unroll 1
    for (int kt = 0; kt < 8; kt++) {
        CP_WAIT1();
        __syncthreads();
        if (kt + 2 < 8)
            load_tile128(sb + ((kt + 2) % 3) * STAGE_BYTES,
                         qp + (kt + 2) * 64, DD, kp + (kt + 2) * 64, DD, tid);
        CP_COMMIT();
        const uint32_t sA = sb + (kt % 3) * STAGE_BYTES;
        const uint32_t sB = sA + TILE_BYTES;
#pragma unroll
        for (int ks = 0; ks < 4; ks++) {
            const int ko = ks * 32 + (lane >> 4) * 16;
            uint32_t a[2][4], bf[8][4];
#pragma unroll
            for (int i = 0; i < 2; i++)
                ldsm4(a[i], sA + (wid * 32 + i * 16 + (lane & 15)) * ROWB + ko);
#pragma unroll
            for (int j = 0; j < 8; j++)
                ldsm4(bf[j], sB + (j * 16 + (lane & 15)) * ROWB + ko);
#pragma unroll
            for (int i = 0; i < 2; i++)
#pragma unroll
                for (int j = 0; j < 8; j++) {
                    mma_bf16(acc[i][2 * j],     a[i], bf[j][0], bf[j][2]);
                    mma_bf16(acc[i][2 * j + 1], a[i], bf[j][1], bf[j][3]);
                }
        }
    }

    // Softmax: thread owns rows wid*32 + i*16 + qr (+8), all 128 cols in quad.
    const int qr = lane >> 2, qc = (lane & 3) * 2;
#pragma unroll
    for (int i = 0; i < 2; i++) {
        const int r0 = wid * 32 + i * 16 + qr, r1 = r0 + 8;
        const float si0 = sq[r0], si1 = sq[r1];

        float m0 = -1e30f, m1 = -1e30f;
#pragma unroll
        for (int n8 = 0; n8 < 16; n8++) {
            const int col = n8 * 8 + qc;
            const float k0 = sk[col], k1 = sk[col + 1];
            acc[i][n8][0] *= si0 * k0; acc[i][n8][1] *= si0 * k1;
            acc[i][n8][2] *= si1 * k0; acc[i][n8][3] *= si1 * k1;
            m0 = fmaxf(m0, fmaxf(acc[i][n8][0], acc[i][n8][1]));
            m1 = fmaxf(m1, fmaxf(acc[i][n8][2], acc[i][n8][3]));
        }
#pragma unroll
        for (int msk = 1; msk <= 2; msk <<= 1) {
            m0 = fmaxf(m0, __shfl_xor_sync(0xffffffffu, m0, msk));
            m1 = fmaxf(m1, __shfl_xor_sync(0xffffffffu, m1, msk));
        }
        float s0 = 0.f, s1 = 0.f;
#pragma unroll
        for (int n8 = 0; n8 < 16; n8++) {
            acc[i][n8][0] = __expf(acc[i][n8][0] - m0); s0 += acc[i][n8][0];
            acc[i][n8][1] = __expf(acc[i][n8][1] - m0); s0 += acc[i][n8][1];
            acc[i][n8][2] = __expf(acc[i][n8][2] - m1); s1 += acc[i][n8][2];
            acc[i][n8][3] = __expf(acc[i][n8][3] - m1); s1 += acc[i][n8][3];
        }
#pragma unroll
        for (int msk = 1; msk <= 2; msk <<= 1) {
            s0 += __shfl_xor_sync(0xffffffffu, s0, msk);
            s1 += __shfl_xor_sync(0xffffffffu, s1, msk);
        }
        const float i0 = 1.0f / s0, i1 = 1.0f / s1;

        float* o0 = out + ALPHA_OFF + (((size_t)b * KK + kb) * NN + r0) * NN;
        float* o1 = out + ALPHA_OFF + (((size_t)b * KK + kb) * NN + r1) * NN;
#pragma unroll
        for (int n8 = 0; n8 < 16; n8++) {
            const int col = n8 * 8 + qc;
            float2 v0 = {acc[i][n8][0] * i0, acc[i][n8][1] * i0};
            float2 v1 = {acc[i][n8][2] * i1, acc[i][n8][3] * i1};
            *(float2*)(o0 + col) = v0;
            *(float2*)(o1 + col) = v1;
        }
    }
}

// ---------------------------------------------------------------------------
// bias_log = log(max(0.01 * mean_b(alpha), 1e-6)) broadcast over b (float4).
// ---------------------------------------------------------------------------
__global__ __launch_bounds__(256) void bias_kernel(float* __restrict__ out) {
    const int v = blockIdx.x * blockDim.x + threadIdx.x;  // float4 index
    if (v >= PLANE / 4) return;
    const size_t idx = (size_t)v * 4;
    float4 s = {0.f, 0.f, 0.f, 0.f};
#pragma unroll 8
    for (int b = 0; b < BB; b++) {
        float4 a = *(const float4*)(out + ALPHA_OFF + (size_t)b * PLANE + idx);
        s.x += a.x; s.y += a.y; s.z += a.z; s.w += a.w;
    }
    const float c = 0.01f / 32.0f;
    float4 bias = {logf(fmaxf(s.x * c, 1e-6f)), logf(fmaxf(s.y * c, 1e-6f)),
                   logf(fmaxf(s.z * c, 1e-6f)), logf(fmaxf(s.w * c, 1e-6f))};
#pragma unroll 8
    for (int b = 0; b < BB; b++)
        *(float4*)(out + (size_t)b * PLANE + idx) = bias;
}

// ---------------------------------------------------------------------------
// Launch
// ---------------------------------------------------------------------------
extern "C" void kernel_launch(void* const* d_in, const int* in_sizes, int n_in,
                              void* d_out, int out_size) {
    const float* desc = (const float*)d_in[0];   // [32,128,512]
    const float* nv   = (const float*)d_in[1];   // [32,128,512]
    const float* Wq   = (const float*)d_in[2];   // [8,512,512]
    const float* Wk   = (const float*)d_in[3];   // [8,512,512]
    const float* fw   = (const float*)d_in[4];   // [512,1024]
    const float* fb   = (const float*)d_in[5];   // [512]
    float* out = (float*)d_out;                  // [bias_log | alpha]

    cudaFuncSetAttribute(fusion_mma_kernel,
                         cudaFuncAttributeMaxDynamicSharedMemorySize, SMEM_BYTES);
    cudaFuncSetAttribute(proj_mma_kernel,
                         cudaFuncAttributeMaxDynamicSharedMemorySize, SMEM_BYTES);
    cudaFuncSetAttribute(attn_mma_kernel,
                         cudaFuncAttributeMaxDynamicSharedMemorySize, SMEM_BYTES);

    // Merged prep: bf16 conversions + W^T -> e4m3 (x16)
    prep_kernel<<<CONV_BLOCKS + 4096, 256>>>(desc, nv, fw, Wq, Wk);

    // fusion = [desc|nv] @ fw^T + fb  (bf16 HMMA) -> e4m3 (x4)
    fusion_mma_kernel<<<dim3(4, 32), 128, SMEM_BYTES>>>(fb);

    // q/k projections in fp8 QMMA (fully unrolled pipeline) + partial sumsq
    proj_mma_kernel<<<dim3(4, 32, 16), 256, SMEM_BYTES>>>();

    // logits + softmax -> alpha (bf16 HMMA + fused norm/softmax epilogue)
    attn_mma_kernel<<<dim3(8, 32), 128, SMEM_BYTES>>>(out);

    // EMA mean + log -> bias_log broadcast (float4)
    bias_kernel<<<PLANE / 4 / 256, 256>>>(out);
}

// round 14
// speedup vs baseline: 1.0435x; 1.0111x over previous
#include <cuda_runtime.h>
#include <cuda_bf16.h>
#include <cuda_fp8.h>
#include <math.h>
#include <stdint.h>

// ---------------------------------------------------------------------------
// Problem constants
// ---------------------------------------------------------------------------
#define BB 32
#define NN 128
#define DD 512
#define KK 8
#define ROWS (BB * NN)                  // 4096
#define PLANE (KK * NN * NN)            // 131072
#define ALPHA_OFF ((size_t)BB * PLANE)  // 4194304

// Shared tile geometry: 128 rows x 128B data + 16B pad = 144B rows.
//   bf16 tiles: 64 k-elements per row; fp8 tiles: 128 k-elements per row.
// Row starts hit word-banks 0,4,...,28 -> conflict-free ldmatrix.
#define ROWB 144
#define TILE_BYTES (128 * ROWB)          // 18432
#define STAGE_BYTES (2 * TILE_BYTES)     // 36864
#define SMEM_BYTES (3 * STAGE_BYTES)     // 110592 (3 stages)

// Scale factors folded into the fp8 operands; they cancel in L2 normalization.
#define FUSED_SCALE 4.0f
#define W_SCALE 16.0f

// ---------------------------------------------------------------------------
// Scratch (static device globals; no cudaMalloc)
// ---------------------------------------------------------------------------
__device__ __nv_bfloat16 g_A0[(size_t)ROWS * 1024];     // concat(desc,nv) bf16
__device__ __nv_bfloat16 g_fwb[(size_t)DD * 1024];      // fusion_w bf16 [d][e]
__device__ uint8_t g_Wt8[(size_t)16 * DD * DD];         // (W^T x16) e4m3 [z][f][d]
__device__ uint8_t g_fused8[(size_t)ROWS * DD];         // (fused x4) e4m3
__device__ __nv_bfloat16 g_qk[(size_t)16 * ROWS * DD];  // q (z<8) then k (x64 scale)
__device__ float g_ss[(size_t)16 * 8 * ROWS];           // partial sumsq [z][p][row]

// ---------------------------------------------------------------------------
// PTX helpers (plain sm_100-safe: HMMA/QMMA mma.sync, ldmatrix, cp.async)
// ---------------------------------------------------------------------------
__device__ __forceinline__ uint32_t smem_u32(const void* p) {
    uint32_t a;
    asm("{ .reg .u64 t; cvta.to.shared.u64 t, %1; cvt.u32.u64 %0, t; }"
        : "=r"(a) : "l"(p));
    return a;
}

__device__ __forceinline__ void cp16(uint32_t dst, const void* src) {
    asm volatile("cp.async.cg.shared.global [%0], [%1], 16;"
                 :: "r"(dst), "l"(src));
}
#define CP_COMMIT() asm volatile("cp.async.commit_group;" ::: "memory")
#define CP_WAIT1()  asm volatile("cp.async.wait_group 1;" ::: "memory")

__device__ __forceinline__ void ldsm4(uint32_t* r, uint32_t addr) {
    asm volatile("ldmatrix.sync.aligned.m8n8.x4.shared.b16 {%0,%1,%2,%3}, [%4];"
                 : "=r"(r[0]), "=r"(r[1]), "=r"(r[2]), "=r"(r[3]) : "r"(addr));
}

__device__ __forceinline__ void mma_bf16(float* d, const uint32_t* a,
                                         uint32_t b0, uint32_t b1) {
    asm volatile(
        "mma.sync.aligned.m16n8k16.row.col.f32.bf16.bf16.f32 "
        "{%0,%1,%2,%3}, {%4,%5,%6,%7}, {%8,%9}, {%0,%1,%2,%3};"
        : "+f"(d[0]), "+f"(d[1]), "+f"(d[2]), "+f"(d[3])
        : "r"(a[0]), "r"(a[1]), "r"(a[2]), "r"(a[3]), "r"(b0), "r"(b1));
}

// fp8 e4m3 MMA: m16n8k32, fp32 accumulate. Fragment layout in b16 units is
// identical to the bf16 m16n8k16 layout (2 packed fp8 = 1 b16 element).
__device__ __forceinline__ void mma_fp8(float* d, const uint32_t* a,
                                        uint32_t b0, uint32_t b1) {
    asm volatile(
        "mma.sync.aligned.m16n8k32.row.col.f32.e4m3.e4m3.f32 "
        "{%0,%1,%2,%3}, {%4,%5,%6,%7}, {%8,%9}, {%0,%1,%2,%3};"
        : "+f"(d[0]), "+f"(d[1]), "+f"(d[2]), "+f"(d[3])
        : "r"(a[0]), "r"(a[1]), "r"(a[2]), "r"(a[3]), "r"(b0), "r"(b1));
}

// Load one 128x64 bf16 A tile + B tile into a smem stage (128 threads).
__device__ __forceinline__ void load_tile128(uint32_t sdst,
                                             const __nv_bfloat16* gA, int ldA,
                                             const __nv_bfloat16* gB, int ldB,
                                             int tid) {
#pragma unroll
    for (int h = 0; h < 8; h++) {
        int c = tid + h * 128;          // 0..1023
        int row = c >> 3, q = c & 7;    // 8 x 16B chunks per 128B row
        cp16(sdst + row * ROWB + q * 16, gA + (size_t)row * ldA + q * 8);
        cp16(sdst + TILE_BYTES + row * ROWB + q * 16,
             gB + (size_t)row * ldB + q * 8);
    }
}

// Load one 128x64 bf16 A tile + B tile into a smem stage (256 threads).
__device__ __forceinline__ void load_tile256(uint32_t sdst,
                                             const __nv_bfloat16* gA, int ldA,
                                             const __nv_bfloat16* gB, int ldB,
                                             int tid) {
#pragma unroll
    for (int h = 0; h < 4; h++) {
        int c = tid + h * 256;          // 0..1023
        int row = c >> 3, q = c & 7;    // 8 x 16B chunks per 128B row
        cp16(sdst + row * ROWB + q * 16, gA + (size_t)row * ldA + q * 8);
        cp16(sdst + TILE_BYTES + row * ROWB + q * 16,
             gB + (size_t)row * ldB + q * 8);
    }
}

// Load one 128x128 fp8 A tile + B tile into a smem stage (256 threads).
__device__ __forceinline__ void load_tile8(uint32_t sdst,
                                           const uint8_t* gA,
                                           const uint8_t* gB, int tid) {
#pragma unroll
    for (int h = 0; h < 4; h++) {
        int c = tid + h * 256;          // 0..1023
        int row = c >> 3, q = c & 7;    // 8 x 16B chunks per 128B row
        cp16(sdst + row * ROWB + q * 16, gA + (size_t)row * DD + q * 16);
        cp16(sdst + TILE_BYTES + row * ROWB + q * 16,
             gB + (size_t)row * DD + q * 16);
    }
}

// ---------------------------------------------------------------------------
// Merged prep kernel: blocks [0, 2304) convert inputs -> bf16;
// blocks [2304, 2304+4096) transpose W -> e4m3 (x16).
// ---------------------------------------------------------------------------
#define CONV_BLOCKS 2304
__global__ __launch_bounds__(256) void prep_kernel(
    const float* __restrict__ desc, const float* __restrict__ nv,
    const float* __restrict__ fw,
    const float* __restrict__ Wq, const float* __restrict__ Wk) {
    if (blockIdx.x < CONV_BLOCKS) {
        size_t base = ((size_t)blockIdx.x * 256 + threadIdx.x) * 8;
        if (base >= (size_t)(ROWS + DD) * 1024) return;
        int r = (int)(base >> 10);
        int c = (int)(base & 1023);
        const float* src;
        __nv_bfloat16* dst;
        if (r < ROWS) {
            src = (c < DD) ? (desc + (size_t)r * DD + c)
                           : (nv + (size_t)r * DD + (c - DD));
            dst = g_A0 + ((size_t)r << 10) + c;
        } else {
            src = fw + (size_t)(r - ROWS) * 1024 + c;
            dst = g_fwb + (size_t)(r - ROWS) * 1024 + c;
        }
        float4 v0 = *(const float4*)src;
        float4 v1 = *(const float4*)(src + 4);
        uint32_t pk[4];
        __nv_bfloat162 h;
        h = __float22bfloat162_rn(make_float2(v0.x, v0.y)); pk[0] = *(uint32_t*)&h;
        h = __float22bfloat162_rn(make_float2(v0.z, v0.w)); pk[1] = *(uint32_t*)&h;
        h = __float22bfloat162_rn(make_float2(v1.x, v1.y)); pk[2] = *(uint32_t*)&h;
        h = __float22bfloat162_rn(make_float2(v1.z, v1.w)); pk[3] = *(uint32_t*)&h;
        *(uint4*)dst = *(uint4*)pk;
    } else {
        __shared__ float t[32][33];
        int blk = blockIdx.x - CONV_BLOCKS;       // 0..4095 = (z*256 + xy)
        int z = blk >> 8;
        int xy = blk & 255;                        // (x*16 + y)
        int d0 = (xy >> 4) * 32, f0 = (xy & 15) * 32;
        const float* W = (z < KK) ? (Wq + (size_t)z * DD * DD)
                                  : (Wk + (size_t)(z - KK) * DD * DD);
        uint8_t* o = g_Wt8 + (size_t)z * DD * DD;
        int tx = threadIdx.x & 31, ty = threadIdx.x >> 5;
#pragma unroll
        for (int j = 0; j < 32; j += 8)
            t[ty + j][tx] = W[(size_t)(d0 + ty + j) * DD + f0 + tx];
        __syncthreads();
#pragma unroll
        for (int j = 0; j < 32; j += 8)
            o[(size_t)(f0 + ty + j) * DD + d0 + tx] =
                __nv_cvt_float_to_fp8(t[tx][ty + j] * W_SCALE,
                                      __NV_SATFINITE, __NV_E4M3);
    }
}

// ---------------------------------------------------------------------------
// Fusion GEMM (bf16 HMMA): 128x128 tile, 2x2 warps, K=1024, fp8 epilogue.
// ---------------------------------------------------------------------------
__device__ __forceinline__ void gemm_2x2_64(
    char* smem, const __nv_bfloat16* gA, int ldA,
    const __nv_bfloat16* gB, int ldB, int KT, float acc[4][8][4]) {
    const uint32_t sb = smem_u32(smem);
    const int tid = threadIdx.x, lane = tid & 31, wid = tid >> 5;
    const int wm = wid >> 1, wn = wid & 1;
    const int lr = lane & 15, lh = (lane >> 4) * 16;

    load_tile128(sb, gA, ldA, gB, ldB, tid);
    CP_COMMIT();
    load_tile128(sb + STAGE_BYTES, gA + 64, ldA, gB + 64, ldB, tid);
    CP_COMMIT();

#pragma unroll 1
    for (int kt = 0; kt < KT; kt++) {
        CP_WAIT1();
        __syncthreads();
        if (kt + 2 < KT)
            load_tile128(sb + ((kt + 2) % 3) * STAGE_BYTES,
                         gA + (kt + 2) * 64, ldA, gB + (kt + 2) * 64, ldB, tid);
        CP_COMMIT();
        const uint32_t stage = sb + (kt % 3) * STAGE_BYTES;
        const uint32_t sA = stage + (wm * 64 + lr) * ROWB + lh;
        const uint32_t sB = stage + TILE_BYTES + (wn * 64 + lr) * ROWB + lh;
#pragma unroll
        for (int ks = 0; ks < 4; ks++) {
            const int ko = ks * 32;
            uint32_t a[4][4], b[4][4];
#pragma unroll
            for (int i = 0; i < 4; i++) ldsm4(a[i], sA + i * (16 * ROWB) + ko);
#pragma unroll
            for (int j = 0; j < 4; j++) ldsm4(b[j], sB + j * (16 * ROWB) + ko);
#pragma unroll
            for (int i = 0; i < 4; i++)
#pragma unroll
                for (int j = 0; j < 4; j++) {
                    mma_bf16(acc[i][2 * j],     a[i], b[j][0], b[j][2]);
                    mma_bf16(acc[i][2 * j + 1], a[i], b[j][1], b[j][3]);
                }
        }
    }
}

__global__ __launch_bounds__(128, 2) void fusion_mma_kernel(
    const float* __restrict__ fb) {
    extern __shared__ char smem[];
    const int bn = blockIdx.x * 128, bm = blockIdx.y * 128;
    const int lane = threadIdx.x & 31, wid = threadIdx.x >> 5;
    const int wm = wid >> 1, wn = wid & 1;
    const int qr = lane >> 2, qc = (lane & 3) * 2;

    float acc[4][8][4];
#pragma unroll
    for (int i = 0; i < 4; i++)
#pragma unroll
        for (int j = 0; j < 8; j++)
#pragma unroll
            for (int e = 0; e < 4; e++) acc[i][j][e] = 0.f;

    gemm_2x2_64(smem, g_A0 + (size_t)bm * 1024, 1024,
                g_fwb + (size_t)bn * 1024, 1024, 16, acc);

    // Epilogue: (acc + bias) * FUSED_SCALE -> e4m3 into g_fused8.
#pragma unroll
    for (int mi = 0; mi < 4; mi++) {
        const int r0 = bm + wm * 64 + mi * 16 + qr;
#pragma unroll
        for (int ni = 0; ni < 8; ni++) {
            const int col = wn * 64 + ni * 8 + qc;
            const float b0 = __ldg(fb + bn + col), b1 = __ldg(fb + bn + col + 1);
            float2 p0 = {(acc[mi][ni][0] + b0) * FUSED_SCALE,
                         (acc[mi][ni][1] + b1) * FUSED_SCALE};
            float2 p1 = {(acc[mi][ni][2] + b0) * FUSED_SCALE,
                         (acc[mi][ni][3] + b1) * FUSED_SCALE};
            __nv_fp8x2_storage_t h0 =
                __nv_cvt_float2_to_fp8x2(p0, __NV_SATFINITE, __NV_E4M3);
            __nv_fp8x2_storage_t h1 =
                __nv_cvt_float2_to_fp8x2(p1, __NV_SATFINITE, __NV_E4M3);
            *(uint16_t*)(g_fused8 + (size_t)r0 * DD + bn + col) = h0;
            *(uint16_t*)(g_fused8 + (size_t)(r0 + 8) * DD + bn + col) = h1;
        }
    }
}

// ---------------------------------------------------------------------------
// Projection GEMM in fp8 (QMMA m16n8k32): 128x128 tile, 4x2 warps
// (warp tile 32x64), K-chunks of 128 fp8, 3-stage cp.async pipeline.
// Outputs q/k (x64 scaled, bf16) + per-row partial sumsq.
// ---------------------------------------------------------------------------
__global__ __launch_bounds__(256, 2) void proj_mma_kernel() {
    extern __shared__ char smem[];
    const int bx = blockIdx.x, bn = bx * 128, bm = blockIdx.y * 128;
    const int z = blockIdx.z;
    const int tid = threadIdx.x, lane = tid & 31, wid = tid >> 5;
    const int wm = wid >> 1, wn = wid & 1;   // wm 0..3, wn 0..1
    const int lr = lane & 15, lh = (lane >> 4) * 16;

    const uint8_t* gA = g_fused8 + (size_t)bm * DD;
    const uint8_t* gB = g_Wt8 + (size_t)z * DD * DD + (size_t)bn * DD;

    float acc[2][8][4];
#pragma unroll
    for (int i = 0; i < 2; i++)
#pragma unroll
        for (int j = 0; j < 8; j++)
#pragma unroll
            for (int e = 0; e < 4; e++) acc[i][j][e] = 0.f;

    const uint32_t sb = smem_u32(smem);
    const uint32_t aoff = (wm * 32 + lr) * ROWB + lh;
    const uint32_t boff = TILE_BYTES + (wn * 64 + lr) * ROWB + lh;

    load_tile8(sb, gA, gB, tid);
    CP_COMMIT();
    load_tile8(sb + STAGE_BYTES, gA + 128, gB + 128, tid);
    CP_COMMIT();

#pragma unroll
    for (int kt = 0; kt < 4; kt++) {
        CP_WAIT1();
        __syncthreads();
        if (kt + 2 < 4)
            load_tile8(sb + ((kt + 2) % 3) * STAGE_BYTES,
                       gA + (kt + 2) * 128, gB + (kt + 2) * 128, tid);
        CP_COMMIT();  // unconditional: keeps wait_group accounting exact
        const uint32_t stage = sb + (kt % 3) * STAGE_BYTES;
        const uint32_t sA = stage + aoff;
        const uint32_t sB = stage + boff;
#pragma unroll
        for (int ks = 0; ks < 4; ks++) {
            const int ko = ks * 32;  // 32 bytes = 32 fp8 = one k32 step
            uint32_t a[2][4], b[4][4];
#pragma unroll
            for (int i = 0; i < 2; i++) ldsm4(a[i], sA + i * (16 * ROWB) + ko);
#pragma unroll
            for (int j = 0; j < 4; j++) ldsm4(b[j], sB + j * (16 * ROWB) + ko);
#pragma unroll
            for (int i = 0; i < 2; i++)
#pragma unroll
                for (int j = 0; j < 4; j++) {
                    mma_fp8(acc[i][2 * j],     a[i], b[j][0], b[j][2]);
                    mma_fp8(acc[i][2 * j + 1], a[i], b[j][1], b[j][3]);
                }
        }
    }

    __nv_bfloat16* outp = g_qk + (size_t)z * ROWS * DD + (size_t)bm * DD + bn;
    float* ssp = g_ss + ((size_t)(z * 8 + bx * 2 + wn) << 12) + bm;
    const int qr = lane >> 2, qc = (lane & 3) * 2;

#pragma unroll
    for (int mi = 0; mi < 2; mi++) {
        const int r0 = wm * 32 + mi * 16 + qr;
        float s0 = 0.f, s1 = 0.f;
#pragma unroll
        for (int ni = 0; ni < 8; ni++) {
            const int col = wn * 64 + ni * 8 + qc;
            const float v0 = acc[mi][ni][0], v1 = acc[mi][ni][1];
            const float v2 = acc[mi][ni][2], v3 = acc[mi][ni][3];
            s0 += v0 * v0 + v1 * v1;
            s1 += v2 * v2 + v3 * v3;
            __nv_bfloat162 h0 = __float22bfloat162_rn(make_float2(v0, v1));
            __nv_bfloat162 h1 = __float22bfloat162_rn(make_float2(v2, v3));
            *(uint32_t*)(outp + (size_t)r0 * DD + col) = *(uint32_t*)&h0;
            *(uint32_t*)(outp + (size_t)(r0 + 8) * DD + col) = *(uint32_t*)&h1;
        }
        s0 += __shfl_xor_sync(0xffffffffu, s0, 1);
        s0 += __shfl_xor_sync(0xffffffffu, s0, 2);
        s1 += __shfl_xor_sync(0xffffffffu, s1, 1);
        s1 += __shfl_xor_sync(0xffffffffu, s1, 2);
        if ((lane & 3) == 0) {
            ssp[r0] = s0;
            ssp[r0 + 8] = s1;
        }
    }
}

// ---------------------------------------------------------------------------
// Attention: 128x128x512 bf16 HMMA + fused norm-scaling/softmax.
// 256 threads, 8 warps, warp tile 16x128: acc is 64 regs/thread, one live
// B fragment at a time -> fits __launch_bounds__(256,2) = 16 warps/SM
// (2x the occupancy of the previous 128-thread version).
// Each output row's 128 values stay inside one warp quad (shfl reductions).
// (q,k carry a consistent x64 scale that cancels in normalization.)
// ---------------------------------------------------------------------------
__global__ __launch_bounds__(256, 2) void attn_mma_kernel(float* __restrict__ out) {
    extern __shared__ char smem[];
    __shared__ float sq[128], sk[128];
    const int kb = blockIdx.x, b = blockIdx.y;
    const int tid = threadIdx.x, lane = tid & 31, wid = tid >> 5;

    const __nv_bfloat16* qp = g_qk + ((size_t)kb * ROWS + (size_t)b * NN) * DD;
    const __nv_bfloat16* kp = g_qk + ((size_t)(KK + kb) * ROWS + (size_t)b * NN) * DD;

    const uint32_t sb = smem_u32(smem);
    load_tile256(sb, qp, DD, kp, DD, tid);
    CP_COMMIT();
    load_tile256(sb + STAGE_BYTES, qp + 64, DD, kp + 64, DD, tid);
    CP_COMMIT();

    // Row norms from partial sums (8 partials per row), overlapped with loads.
    if (tid < 128) {
        const float SCALE = 0.04419417382415922f;  // 1/sqrt(512)
        float s0 = 0.f, s1 = 0.f;
#pragma unroll
        for (int p = 0; p < 8; p++) {
            s0 += g_ss[((size_t)(kb * 8 + p) << 12) + b * NN + tid];
            s1 += g_ss[((size_t)((KK + kb) * 8 + p) << 12) + b * NN + tid];
        }
        sq[tid] = SCALE / fmaxf(sqrtf(s0), 1e-12f);
        sk[tid] = 1.0f / fmaxf(sqrtf(s1), 1e-12f);
    }

    float acc[16][4];
#pragma unroll
    for (int j = 0; j < 16; j++)
#pragma unroll
        for (int e = 0; e < 4; e++) acc[j][e] = 0.f;

    const int lr = lane & 15, lh = (lane >> 4) * 16;
    const uint32_t aoff = (wid * 16 + lr) * ROWB + lh;
    const uint32_t boff = TILE_BYTES + lr * ROWB + lh;

#pragma unroll 1
    for (int kt = 0; kt < 8; kt++) {
        CP_WAIT1();
        __syncthreads();
        if (kt + 2 < 8)
            load_tile256(sb + ((kt + 2) % 3) * STAGE_BYTES,
                         qp + (kt + 2) * 64, DD, kp + (kt + 2) * 64, DD, tid);
        CP_COMMIT();
        const uint32_t stage = sb + (kt % 3) * STAGE_BYTES;
        const uint32_t sA = stage + aoff;
        const uint32_t sB = stage + boff;
#pragma unroll
        for (int ks = 0; ks < 4; ks++) {
            const int ko = ks * 32;
            uint32_t a[4];
            ldsm4(a, sA + ko);
#pragma unroll
            for (int j = 0; j < 8; j++) {
                uint32_t bf[4];
                ldsm4(bf, sB + j * (16 * ROWB) + ko);
                mma_bf16(acc[2 * j],     a, bf[0], bf[2]);
                mma_bf16(acc[2 * j + 1], a, bf[1], bf[3]);
            }
        }
    }

    // Softmax: thread owns rows wid*16 + qr and +8; all 128 cols in its quad.
    const int qr = lane >> 2, qc = (lane & 3) * 2;
    const int r0 = wid * 16 + qr, r1 = r0 + 8;
    const float si0 = sq[r0], si1 = sq[r1];

    float m0 = -1e30f, m1 = -1e30f;
#pragma unroll
    for (int n8 = 0; n8 < 16; n8++) {
        const int col = n8 * 8 + qc;
        const float k0 = sk[col], k1 = sk[col + 1];
        acc[n8][0] *= si0 * k0; acc[n8][1] *= si0 * k1;
        acc[n8][2] *= si1 * k0; acc[n8][3] *= si1 * k1;
        m0 = fmaxf(m0, fmaxf(acc[n8][0], acc[n8][1]));
        m1 = fmaxf(m1, fmaxf(acc[n8][2], acc[n8][3]));
    }
#pragma unroll
    for (int msk = 1; msk <= 2; msk <<= 1) {
        m0 = fmaxf(m0, __shfl_xor_sync(0xffffffffu, m0, msk));
        m1 = fmaxf(m1, __shfl_xor_sync(0xffffffffu, m1, msk));
    }
    float s0 = 0.f, s1 = 0.f;
#pragma unroll
    for (int n8 = 0; n8 < 16; n8++) {
        acc[n8][0] = __expf(acc[n8][0] - m0); s0 += acc[n8][0];
        acc[n8][1] = __expf(acc[n8][1] - m0); s0 += acc[n8][1];
        acc[n8][2] = __expf(acc[n8][2] - m1); s1 += acc[n8][2];
        acc[n8][3] = __expf(acc[n8][3] - m1); s1 += acc[n8][3];
    }
#pragma unroll
    for (int msk = 1; msk <= 2; msk <<= 1) {
        s0 += __shfl_xor_sync(0xffffffffu, s0, msk);
        s1 += __shfl_xor_sync(0xffffffffu, s1, msk);
    }
    const float i0 = 1.0f / s0, i1 = 1.0f / s1;

    float* o0 = out + ALPHA_OFF + (((size_t)b * KK + kb) * NN + r0) * NN;
    float* o1 = out + ALPHA_OFF + (((size_t)b * KK + kb) * NN + r1) * NN;
#pragma unroll
    for (int n8 = 0; n8 < 16; n8++) {
        const int col = n8 * 8 + qc;
        float2 v0 = {acc[n8][0] * i0, acc[n8][1] * i0};
        float2 v1 = {acc[n8][2] * i1, acc[n8][3] * i1};
        *(float2*)(o0 + col) = v0;
        *(float2*)(o1 + col) = v1;
    }
}

// ---------------------------------------------------------------------------
// bias_log = log(max(0.01 * mean_b(alpha), 1e-6)) broadcast over b (float4).
// ---------------------------------------------------------------------------
__global__ __launch_bounds__(256) void bias_kernel(float* __restrict__ out) {
    const int v = blockIdx.x * blockDim.x + threadIdx.x;  // float4 index
    if (v >= PLANE / 4) return;
    const size_t idx = (size_t)v * 4;
    float4 s = {0.f, 0.f, 0.f, 0.f};
#pragma unroll 8
    for (int b = 0; b < BB; b++) {
        float4 a = *(const float4*)(out + ALPHA_OFF + (size_t)b * PLANE + idx);
        s.x += a.x; s.y += a.y; s.z += a.z; s.w += a.w;
    }
    const float c = 0.01f / 32.0f;
    float4 bias = {logf(fmaxf(s.x * c, 1e-6f)), logf(fmaxf(s.y * c, 1e-6f)),
                   logf(fmaxf(s.z * c, 1e-6f)), logf(fmaxf(s.w * c, 1e-6f))};
#pragma unroll 8
    for (int b = 0; b < BB; b++)
        *(float4*)(out + (size_t)b * PLANE + idx) = bias;
}

// ---------------------------------------------------------------------------
// Launch
// ---------------------------------------------------------------------------
extern "C" void kernel_launch(void* const* d_in, const int* in_sizes, int n_in,
                              void* d_out, int out_size) {
    const float* desc = (const float*)d_in[0];   // [32,128,512]
    const float* nv   = (const float*)d_in[1];   // [32,128,512]
    const float* Wq   = (const float*)d_in[2];   // [8,512,512]
    const float* Wk   = (const float*)d_in[3];   // [8,512,512]
    const float* fw   = (const float*)d_in[4];   // [512,1024]
    const float* fb   = (const float*)d_in[5];   // [512]
    float* out = (float*)d_out;                  // [bias_log | alpha]

    cudaFuncSetAttribute(fusion_mma_kernel,
                         cudaFuncAttributeMaxDynamicSharedMemorySize, SMEM_BYTES);
    cudaFuncSetAttribute(proj_mma_kernel,
                         cudaFuncAttributeMaxDynamicSharedMemorySize, SMEM_BYTES);
    cudaFuncSetAttribute(attn_mma_kernel,
                         cudaFuncAttributeMaxDynamicSharedMemorySize, SMEM_BYTES);

    // Merged prep: bf16 conversions + W^T -> e4m3 (x16)
    prep_kernel<<<CONV_BLOCKS + 4096, 256>>>(desc, nv, fw, Wq, Wk);

    // fusion = [desc|nv] @ fw^T + fb  (bf16 HMMA) -> e4m3 (x4)
    fusion_mma_kernel<<<dim3(4, 32), 128, SMEM_BYTES>>>(fb);

    // q/k projections in fp8 QMMA + fused partial row-sumsq
    proj_mma_kernel<<<dim3(4, 32, 16), 256, SMEM_BYTES>>>();

    // logits + softmax -> alpha (bf16 HMMA, 256 threads, 16 warps/SM)
    attn_mma_kernel<<<dim3(8, 32), 256, SMEM_BYTES>>>(out);

    // EMA mean + log -> bias_log broadcast (float4)
    bias_kernel<<<PLANE / 4 / 256, 256>>>(out);
}